// round 8
// baseline (speedup 1.0000x reference)
#include <cuda_runtime.h>
#include <cstdint>

#define N_NODES  100000
#define N_EDGES  1000000
#define HID      64
#define EDGE_D   32
#define N_GRAPHS 256
#define SCAN_BLK 1024
#define N_SCAN_BLKS ((N_NODES + SCAN_BLK - 1) / SCAN_BLK)   // 98

#define CV_T 512
#define CV_EDGE_BLKS  ((N_EDGES + CV_T - 1) / CV_T)          // 1954
#define CV_BATCH_BLKS ((N_NODES + CV_T - 1) / CV_T)          // 196

// ---------------- scratch (static device globals; no allocation) -------------
// Everything needing per-launch zeroing lives in one struct -> ONE memset.
struct Zeroed {
    int          cnt[N_NODES];            // in-degree histogram
    float        gsum[N_GRAPHS * HID];    // graph pool numerators
    float        gcnt[N_GRAPHS];          // graph node counts
    unsigned int bflag[N_SCAN_BLKS];      // scan aggregates (bit31 = published)
};
__device__ Zeroed g_z;

__device__ float g_h[N_NODES * HID];      // node features after lin (per layer)
__device__ float g_agg0[N_NODES * HID];   // layer0 NORMALIZED aggregate
__device__ float g_as[N_NODES];           // source attention logits
__device__ float g_ad[N_NODES];           // dest attention logits
__device__ float g_we0[EDGE_D];           // We0 @ att_edge0
__device__ float g_we1[EDGE_D];           // We1 @ att_edge1
__device__ int   g_src[N_EDGES];
__device__ int   g_dst[N_EDGES];
__device__ int   g_batch[N_NODES];
__device__ int   g_off[N_NODES + 1];      // CSR offsets
__device__ int   g_cur[N_NODES];          // scatter cursors
__device__ float4 g_edges[N_EDGES];       // packed {src_bits, ae0, ae1, pad}, dst-sorted

// ---------------- vectorized global reductions (sm_90+) ----------------------
__device__ __forceinline__ void red_add_v4(float* addr, float x, float y, float z, float w) {
    asm volatile(
        "{ .reg .u64 a; cvta.to.global.u64 a, %0; red.global.add.v4.f32 [a], {%1,%2,%3,%4}; }"
        :: "l"(addr), "f"(x), "f"(y), "f"(z), "f"(w) : "memory");
}
__device__ __forceinline__ void red_add_f32(float* addr, float x) {
    asm volatile(
        "{ .reg .u64 a; cvta.to.global.u64 a, %0; red.global.add.f32 [a], %1; }"
        :: "l"(addr), "f"(x) : "memory");
}

// ---------------- per-warp dtype detection (int32 vs int64 indices) ----------
// Reads 32 int64-candidate slots from the edge SRC region (bytes < 8MB: safe
// under both interpretations). If data is int32, hi words hold src[2i+1]
// (nonzero w.p. 1-1e-5 each); genuine int64 ids < 2^31 have hi == 0.
__device__ __forceinline__ bool detect_is32(const void* ei_raw) {
    const uint2* w = (const uint2*)ei_raw;
    int lane = threadIdx.x & 31;
    uint2 probe = __ldg(&w[lane]);
    unsigned m = __ballot_sync(0xffffffffu, probe.y != 0u);
    return m != 0u;
}

// ---------------- fused convert: edges + histogram + batch + prep_we ---------
__global__ void convert_all_kernel(const void* __restrict__ ei_raw,
                                   const void* __restrict__ ba_raw,
                                   const float* __restrict__ We0, const float* __restrict__ ae0,
                                   const float* __restrict__ We1, const float* __restrict__ ae1) {
    int b = blockIdx.x;
    bool is32 = detect_is32(ei_raw);

    if (b < CV_EDGE_BLKS) {
        int e = b * CV_T + threadIdx.x;
        if (e >= N_EDGES) return;
        int s, d;
        if (is32) {
            const int* p = (const int*)ei_raw;
            s = p[e]; d = p[N_EDGES + e];
        } else {
            const long long* p = (const long long*)ei_raw;
            s = (int)p[e]; d = (int)p[N_EDGES + e];
        }
        g_src[e] = s;
        g_dst[e] = d;
        atomicAdd(&g_z.cnt[d], 1);
    } else if (b < CV_EDGE_BLKS + CV_BATCH_BLKS) {
        int n = (b - CV_EDGE_BLKS) * CV_T + threadIdx.x;
        if (n >= N_NODES) return;
        int g;
        if (is32) g = ((const int*)ba_raw)[n];
        else      g = (int)((const long long*)ba_raw)[n];
        g_batch[n] = g;
        red_add_f32(&g_z.gcnt[g], 1.0f);
    } else {
        // prep_we: w_e = We @ att_e for both layers
        int t = threadIdx.x;
        if (t < EDGE_D) {
            float s = 0.f;
            #pragma unroll
            for (int j = 0; j < HID; j++) s += We0[t * HID + j] * ae0[j];
            g_we0[t] = s;
        } else if (t < 2 * EDGE_D) {
            int r = t - EDGE_D;
            float s = 0.f;
            #pragma unroll
            for (int j = 0; j < HID; j++) s += We1[r * HID + j] * ae1[j];
            g_we1[r] = s;
        }
    }
}

// ---------------- single-kernel exclusive scan (decoupled lookback) ----------
// 98 blocks, all co-resident (100k threads << chip capacity): each block does
// a shuffle-based local scan, publishes its aggregate with a flag bit, then
// warp 0 polls+sums all predecessor aggregates.
__global__ void scan_kernel() {
    __shared__ int wsum[32];
    __shared__ int s_base;
    int tid  = threadIdx.x;
    int lane = tid & 31;
    int warp = tid >> 5;
    int b    = blockIdx.x;
    int i    = b * SCAN_BLK + tid;

    int v = (i < N_NODES) ? g_z.cnt[i] : 0;

    // warp inclusive scan
    int x = v;
    #pragma unroll
    for (int o = 1; o < 32; o <<= 1) {
        int t = __shfl_up_sync(0xffffffffu, x, o);
        if (lane >= o) x += t;
    }
    if (lane == 31) wsum[warp] = x;
    __syncthreads();
    if (warp == 0) {
        int ws = wsum[lane];
        #pragma unroll
        for (int o = 1; o < 32; o <<= 1) {
            int t = __shfl_up_sync(0xffffffffu, ws, o);
            if (lane >= o) ws += t;
        }
        wsum[lane] = ws;                   // inclusive warp sums
    }
    __syncthreads();

    int excl   = ((warp > 0) ? wsum[warp - 1] : 0) + x - v;   // block-exclusive
    int btotal = wsum[31];

    if (tid == 0)
        atomicExch(&g_z.bflag[b], (unsigned)btotal | 0x80000000u);

    // lookback: warp 0 sums predecessors' aggregates
    if (warp == 0) {
        int sum = 0;
        for (int p = lane; p < b; p += 32) {
            unsigned f;
            do { f = atomicOr(&g_z.bflag[p], 0u); } while (!(f & 0x80000000u));
            sum += (int)(f & 0x7fffffffu);
        }
        #pragma unroll
        for (int o = 16; o > 0; o >>= 1)
            sum += __shfl_xor_sync(0xffffffffu, sum, o);
        if (lane == 0) s_base = sum;
    }
    __syncthreads();

    if (i < N_NODES) {
        int o = s_base + excl;
        g_off[i] = o;
        g_cur[i] = o;
    }
    if (i == 0) g_off[N_NODES] = N_EDGES;
}

// ---------------- CSR build: bucket-scatter packed edge records --------------
__global__ void build_csr_kernel(const float* __restrict__ ea) {
    __shared__ float sw0[EDGE_D];
    __shared__ float sw1[EDGE_D];
    int tid = threadIdx.x;
    if (tid < EDGE_D) sw0[tid] = g_we0[tid];
    else if (tid < 2 * EDGE_D) sw1[tid - EDGE_D] = g_we1[tid - EDGE_D];
    __syncthreads();

    int e = blockIdx.x * blockDim.x + tid;
    if (e >= N_EDGES) return;

    const float4* row = (const float4*)(ea + (size_t)e * EDGE_D);
    float ae0 = 0.f, ae1 = 0.f;
    #pragma unroll
    for (int i = 0; i < EDGE_D / 4; i++) {
        float4 v = __ldg(&row[i]);
        ae0 += v.x * sw0[4*i] + v.y * sw0[4*i+1] + v.z * sw0[4*i+2] + v.w * sw0[4*i+3];
        ae1 += v.x * sw1[4*i] + v.y * sw1[4*i+1] + v.z * sw1[4*i+2] + v.w * sw1[4*i+3];
    }

    int d = g_dst[e];
    int pos = atomicAdd(&g_cur[d], 1);
    g_edges[pos] = make_float4(__int_as_float(g_src[e]), ae0, ae1, 0.f);
}

// ---------------- node GEMM + attention dots ---------------------------------
__global__ void node_gemm_kernel(const float* __restrict__ xin,
                                 const float* __restrict__ addb,   // may be null
                                 const float* __restrict__ W,
                                 const float* __restrict__ atts,
                                 const float* __restrict__ attd,
                                 float* __restrict__ hout,
                                 float* __restrict__ as_out,
                                 float* __restrict__ ad_out) {
    __shared__ float Wsh[HID * HID];
    __shared__ float xsh[4 * HID];
    __shared__ float ssh[HID];
    __shared__ float dsh[HID];
    __shared__ float red_s[8];
    __shared__ float red_d[8];

    int tid  = threadIdx.x;
    int j    = tid & 63;
    int sub  = tid >> 6;
    int warp = tid >> 5;

    for (int i = tid; i < HID * HID; i += 256) Wsh[i] = W[i];
    if (tid < HID) { ssh[tid] = atts[tid]; dsh[tid] = attd[tid]; }
    __syncthreads();

    float wreg[HID];
    #pragma unroll
    for (int k = 0; k < HID; k++) wreg[k] = Wsh[k * HID + j];

    float bcol = (addb != nullptr) ? addb[j] : 0.f;

    for (int base = blockIdx.x * 4; base < N_NODES; base += gridDim.x * 4) {
        __syncthreads();
        xsh[tid] = xin[base * HID + tid] + bcol;
        __syncthreads();

        float acc = 0.f;
        const float* xr = &xsh[sub * HID];
        #pragma unroll
        for (int k = 0; k < HID; k++) acc += xr[k] * wreg[k];

        hout[base * HID + tid] = acc;

        float sv = acc * ssh[j];
        float dv = acc * dsh[j];
        #pragma unroll
        for (int off = 16; off > 0; off >>= 1) {
            sv += __shfl_down_sync(0xffffffffu, sv, off);
            dv += __shfl_down_sync(0xffffffffu, dv, off);
        }
        if ((tid & 31) == 0) { red_s[warp] = sv; red_d[warp] = dv; }
        __syncthreads();
        if (tid < 4) {
            as_out[base + tid] = red_s[2 * tid] + red_s[2 * tid + 1];
            ad_out[base + tid] = red_d[2 * tid] + red_d[2 * tid + 1];
        }
    }
}

// ---------------- gather-only attention aggregate (atomic-free) --------------
// Warp per dst node; FOUR quarter-warp chains split its edges (~2.5 iters at
// mean degree 10 -> 4x MLP). Lane l (0..7) owns feature cols [8l, 8l+8).
// LAYER==0: writes normalized agg. LAYER==1: fuses residual+bias+pool.
template<int LAYER>
__global__ void agg_kernel(const float* __restrict__ h,
                           float* __restrict__ aggout,
                           const float* __restrict__ b0,
                           const float* __restrict__ b1) {
    int warp = (blockIdx.x * blockDim.x + threadIdx.x) >> 5;
    int lane = threadIdx.x & 31;
    int q    = lane >> 3;      // chain 0..3
    int l    = lane & 7;       // feature octet
    int n    = warp;
    if (n >= N_NODES) return;

    int start = g_off[n];
    int end   = g_off[n + 1];
    float adn = g_ad[n];

    float4 accA = make_float4(0.f, 0.f, 0.f, 0.f);
    float4 accB = make_float4(0.f, 0.f, 0.f, 0.f);
    float  dacc = 0.f;

    for (int i = start + q; i < end; i += 4) {
        float4 er = g_edges[i];                     // broadcast across 8 lanes
        int   src = __float_as_int(er.x);
        float ae  = (LAYER == 0) ? er.y : er.z;
        const float4* hrow = (const float4*)h + (size_t)src * 16;
        float4 ha = hrow[2 * l];
        float4 hb = hrow[2 * l + 1];
        float al = g_as[src] + adn + ae;
        al = (al > 0.f) ? al : 0.2f * al;           // leaky relu
        float p = __expf(al);                       // no max-sub (softmax invariant)
        accA.x += p * ha.x; accA.y += p * ha.y; accA.z += p * ha.z; accA.w += p * ha.w;
        accB.x += p * hb.x; accB.y += p * hb.y; accB.z += p * hb.z; accB.w += p * hb.w;
        dacc   += p;
    }

    // combine the four chains (xor over chain bits 8 and 16)
    #pragma unroll
    for (int o = 8; o <= 16; o <<= 1) {
        accA.x += __shfl_xor_sync(0xffffffffu, accA.x, o);
        accA.y += __shfl_xor_sync(0xffffffffu, accA.y, o);
        accA.z += __shfl_xor_sync(0xffffffffu, accA.z, o);
        accA.w += __shfl_xor_sync(0xffffffffu, accA.w, o);
        accB.x += __shfl_xor_sync(0xffffffffu, accB.x, o);
        accB.y += __shfl_xor_sync(0xffffffffu, accB.y, o);
        accB.z += __shfl_xor_sync(0xffffffffu, accB.z, o);
        accB.w += __shfl_xor_sync(0xffffffffu, accB.w, o);
        dacc   += __shfl_xor_sync(0xffffffffu, dacc,   o);
    }

    if (q == 0) {
        float r = 1.f / (dacc + 1e-16f);
        if (LAYER == 0) {
            float4* dst = (float4*)aggout + (size_t)n * 16;
            dst[2 * l]     = make_float4(accA.x * r, accA.y * r, accA.z * r, accA.w * r);
            dst[2 * l + 1] = make_float4(accB.x * r, accB.y * r, accB.z * r, accB.w * r);
        } else {
            const float4* v0 = (const float4*)g_agg0 + (size_t)n * 16;
            float4 vA = v0[2 * l], vB = v0[2 * l + 1];
            float4 bA0 = ((const float4*)b0)[2 * l], bB0 = ((const float4*)b0)[2 * l + 1];
            float4 bA1 = ((const float4*)b1)[2 * l], bB1 = ((const float4*)b1)[2 * l + 1];
            int g = g_batch[n];
            float* gs = &g_z.gsum[g * HID];
            red_add_v4(gs + 8 * l,
                       accA.x * r + vA.x + bA0.x + bA1.x,
                       accA.y * r + vA.y + bA0.y + bA1.y,
                       accA.z * r + vA.z + bA0.z + bA1.z,
                       accA.w * r + vA.w + bA0.w + bA1.w);
            red_add_v4(gs + 8 * l + 4,
                       accB.x * r + vB.x + bB0.x + bB1.x,
                       accB.y * r + vB.y + bB0.y + bB1.y,
                       accB.z * r + vB.z + bB0.z + bB1.z,
                       accB.w * r + vB.w + bB0.w + bB1.w);
        }
    }
}

__global__ void finalize_kernel(float* __restrict__ out) {
    int i = blockIdx.x * HID + threadIdx.x;   // 256 blocks x 64 threads
    int g = i >> 6;
    float c = g_z.gcnt[g];
    if (c < 1.f) c = 1.f;
    out[i] = g_z.gsum[i] / c;
}

// ---------------- launcher ---------------------------------------------------
extern "C" void kernel_launch(void* const* d_in, const int* in_sizes, int n_in,
                              void* d_out, int out_size) {
    const float* x     = (const float*)d_in[0];
    const void*  ei    = d_in[1];
    const float* ea    = (const float*)d_in[2];
    const void*  batch = d_in[3];
    const float* W0   = (const float*)d_in[4];
    const float* as0  = (const float*)d_in[5];
    const float* ad0  = (const float*)d_in[6];
    const float* We0  = (const float*)d_in[7];
    const float* ae0v = (const float*)d_in[8];
    const float* b0   = (const float*)d_in[9];
    const float* W1   = (const float*)d_in[10];
    const float* as1  = (const float*)d_in[11];
    const float* ad1  = (const float*)d_in[12];
    const float* We1  = (const float*)d_in[13];
    const float* ae1v = (const float*)d_in[14];
    const float* b1   = (const float*)d_in[15];
    float* out = (float*)d_out;

    void *p_z, *p_h, *p_as, *p_ad, *p_agg0;
    cudaGetSymbolAddress(&p_z,    g_z);
    cudaGetSymbolAddress(&p_h,    g_h);
    cudaGetSymbolAddress(&p_as,   g_as);
    cudaGetSymbolAddress(&p_ad,   g_ad);
    cudaGetSymbolAddress(&p_agg0, g_agg0);

    float* hbuf = (float*)p_h;
    float* asb  = (float*)p_as;
    float* adb  = (float*)p_ad;

    // ONE memset for all per-launch-zeroed state
    cudaMemsetAsync(p_z, 0, sizeof(Zeroed));

    // fused conversion (edges + histogram + batch + prep_we)
    convert_all_kernel<<<CV_EDGE_BLKS + CV_BATCH_BLKS + 1, CV_T>>>(
        ei, batch, We0, ae0v, We1, ae1v);

    // single-kernel scan + CSR build
    scan_kernel<<<N_SCAN_BLKS, SCAN_BLK>>>();
    build_csr_kernel<<<(N_EDGES + 255) / 256, 256>>>(ea);

    // ---- layer 0 ----
    node_gemm_kernel<<<1184, 256>>>(x, nullptr, W0, as0, ad0, hbuf, asb, adb);
    agg_kernel<0><<<(N_NODES * 32 + 255) / 256, 256>>>(hbuf, (float*)p_agg0, b0, b1);

    // ---- layer 1 (input = normalized agg0 + b0, fused into gemm load;
    //      agg pass fuses residual + bias + pool) ----
    node_gemm_kernel<<<1184, 256>>>((const float*)p_agg0, b0, W1, as1, ad1, hbuf, asb, adb);
    agg_kernel<1><<<(N_NODES * 32 + 255) / 256, 256>>>(hbuf, nullptr, b0, b1);

    // ---- finalize (divide by per-graph counts) ----
    finalize_kernel<<<N_GRAPHS, HID>>>(out);
}

// round 9
// speedup vs baseline: 1.2772x; 1.2772x over previous
#include <cuda_runtime.h>
#include <cstdint>

#define N_NODES  100000
#define N_EDGES  1000000
#define HID      64
#define EDGE_D   32
#define N_GRAPHS 256
#define SCAN_BLK 1024
#define N_SCAN_BLKS ((N_NODES + SCAN_BLK - 1) / SCAN_BLK)   // 98

// ---------------- scratch (static device globals; no allocation) -------------
__device__ float g_h[N_NODES * HID];      // node features after lin (per layer)
__device__ float g_agg0[N_NODES * HID];   // layer0 NORMALIZED aggregate
__device__ float g_as[N_NODES];           // source attention logits
__device__ float g_ad[N_NODES];           // dest attention logits
__device__ float g_we0[EDGE_D];           // We0 @ att_edge0
__device__ float g_we1[EDGE_D];           // We1 @ att_edge1
__device__ float g_ws0[HID];              // W0 @ att_src0
__device__ float g_wd0[HID];              // W0 @ att_dst0
__device__ float g_ws1[HID];              // W1 @ att_src1
__device__ float g_wd1[HID];              // W1 @ att_dst1
__device__ float g_gsum[N_GRAPHS * HID];
__device__ float g_gcnt[N_GRAPHS];
__device__ int   g_src[N_EDGES];
__device__ int   g_dst[N_EDGES];
__device__ int   g_batch[N_NODES];
__device__ int   g_is32;
__device__ int   g_cnt[N_NODES];          // in-degree histogram
__device__ int   g_off[N_NODES + 1];      // CSR offsets
__device__ int   g_cur[N_NODES];          // scatter cursors
__device__ int   g_bsum[128];             // scan block sums
__device__ int   g_bexcl[128];            // scanned block sums
__device__ float4 g_edges[N_EDGES];       // packed {src_bits, ae0, ae1, pad}, dst-sorted

// ---------------- vectorized global reductions (sm_90+) ----------------------
__device__ __forceinline__ void red_add_v4(float* addr, float x, float y, float z, float w) {
    asm volatile(
        "{ .reg .u64 a; cvta.to.global.u64 a, %0; red.global.add.v4.f32 [a], {%1,%2,%3,%4}; }"
        :: "l"(addr), "f"(x), "f"(y), "f"(z), "f"(w) : "memory");
}
__device__ __forceinline__ void red_add_f32(float* addr, float x) {
    asm volatile(
        "{ .reg .u64 a; cvta.to.global.u64 a, %0; red.global.add.f32 [a], %1; }"
        :: "l"(addr), "f"(x) : "memory");
}

// ---------------- dtype detection: int32 vs int64 edge_index -----------------
__global__ void detect_dtype_kernel(const void* __restrict__ ei_raw) {
    const unsigned int* w = (const unsigned int*)ei_raw;
    int t = threadIdx.x;
    unsigned int hi = w[2 * t + 1];
    unsigned int any = __syncthreads_or(hi != 0u);
    if (t == 0) g_is32 = (any != 0u) ? 1 : 0;
}

// convert indices + build in-degree histogram
__global__ void convert_edges_kernel(const void* __restrict__ ei_raw) {
    int e = blockIdx.x * blockDim.x + threadIdx.x;
    if (e >= N_EDGES) return;
    int s, d;
    if (g_is32) {
        const int* p = (const int*)ei_raw;
        s = p[e]; d = p[N_EDGES + e];
    } else {
        const long long* p = (const long long*)ei_raw;
        s = (int)p[e]; d = (int)p[N_EDGES + e];
    }
    g_src[e] = s;
    g_dst[e] = d;
    atomicAdd(&g_cnt[d], 1);
}

// convert batch indices + accumulate per-graph node counts
__global__ void convert_batch_kernel(const void* __restrict__ b_raw) {
    int n = blockIdx.x * blockDim.x + threadIdx.x;
    if (n >= N_NODES) return;
    int g;
    if (g_is32) g = ((const int*)b_raw)[n];
    else        g = (int)((const long long*)b_raw)[n];
    g_batch[n] = g;
    red_add_f32(&g_gcnt[g], 1.0f);
}

// ---------------- 2-level exclusive scan of g_cnt -> g_off -------------------
__global__ void scan1_kernel() {
    __shared__ int sh[SCAN_BLK];
    int tid = threadIdx.x;
    int i = blockIdx.x * SCAN_BLK + tid;
    int v = (i < N_NODES) ? g_cnt[i] : 0;
    sh[tid] = v;
    __syncthreads();
    for (int ofs = 1; ofs < SCAN_BLK; ofs <<= 1) {
        int t = (tid >= ofs) ? sh[tid - ofs] : 0;
        __syncthreads();
        sh[tid] += t;
        __syncthreads();
    }
    if (i < N_NODES) g_off[i] = sh[tid] - v;       // exclusive within block
    if (tid == SCAN_BLK - 1) g_bsum[blockIdx.x] = sh[tid];
}

__global__ void scan2_kernel() {
    __shared__ int sh[128];
    int tid = threadIdx.x;
    int v = (tid < N_SCAN_BLKS) ? g_bsum[tid] : 0;
    sh[tid] = v;
    __syncthreads();
    for (int ofs = 1; ofs < 128; ofs <<= 1) {
        int t = (tid >= ofs) ? sh[tid - ofs] : 0;
        __syncthreads();
        sh[tid] += t;
        __syncthreads();
    }
    g_bexcl[tid] = sh[tid] - v;                    // exclusive
}

__global__ void scan3_kernel() {
    int i = blockIdx.x * SCAN_BLK + threadIdx.x;
    if (i < N_NODES) {
        int o = g_off[i] + g_bexcl[blockIdx.x];
        g_off[i] = o;
        g_cur[i] = o;
    }
    if (i == 0) g_off[N_NODES] = N_EDGES;
}

// ---------------- precompute folded attention vectors ------------------------
// we = We @ att_e (per layer); ws = W @ att_s; wd = W @ att_d (per layer).
// a_s = (x@W)@att_s == x@(W@att_s)  — removes in-GEMM reductions entirely.
__global__ void prep_kernel(const float* __restrict__ We0, const float* __restrict__ ae0,
                            const float* __restrict__ We1, const float* __restrict__ ae1,
                            const float* __restrict__ W0,  const float* __restrict__ as0,
                            const float* __restrict__ ad0,
                            const float* __restrict__ W1,  const float* __restrict__ as1,
                            const float* __restrict__ ad1) {
    int t = threadIdx.x;   // 64 threads
    if (t < EDGE_D) {
        float s0 = 0.f, s1 = 0.f;
        #pragma unroll
        for (int j = 0; j < HID; j++) {
            s0 += We0[t * HID + j] * ae0[j];
            s1 += We1[t * HID + j] * ae1[j];
        }
        g_we0[t] = s0;
        g_we1[t] = s1;
    }
    float vs0 = 0.f, vd0 = 0.f, vs1 = 0.f, vd1 = 0.f;
    #pragma unroll
    for (int j = 0; j < HID; j++) {
        float w0 = W0[t * HID + j];
        float w1 = W1[t * HID + j];
        vs0 += w0 * as0[j];  vd0 += w0 * ad0[j];
        vs1 += w1 * as1[j];  vd1 += w1 * ad1[j];
    }
    g_ws0[t] = vs0;  g_wd0[t] = vd0;
    g_ws1[t] = vs1;  g_wd1[t] = vd1;
}

// ---------------- CSR build: bucket-scatter packed edge records --------------
__global__ void build_csr_kernel(const float* __restrict__ ea) {
    __shared__ float sw0[EDGE_D];
    __shared__ float sw1[EDGE_D];
    int tid = threadIdx.x;
    if (tid < EDGE_D) sw0[tid] = g_we0[tid];
    else if (tid < 2 * EDGE_D) sw1[tid - EDGE_D] = g_we1[tid - EDGE_D];
    __syncthreads();

    int e = blockIdx.x * blockDim.x + tid;
    if (e >= N_EDGES) return;

    const float4* row = (const float4*)(ea + (size_t)e * EDGE_D);
    float ae0 = 0.f, ae1 = 0.f;
    #pragma unroll
    for (int i = 0; i < EDGE_D / 4; i++) {
        float4 v = __ldg(&row[i]);
        ae0 += v.x * sw0[4*i] + v.y * sw0[4*i+1] + v.z * sw0[4*i+2] + v.w * sw0[4*i+3];
        ae1 += v.x * sw1[4*i] + v.y * sw1[4*i+1] + v.z * sw1[4*i+2] + v.w * sw1[4*i+3];
    }

    int d = g_dst[e];
    int pos = atomicAdd(&g_cur[d], 1);
    g_edges[pos] = make_float4(__int_as_float(g_src[e]), ae0, ae1, 0.f);
}

// ---------------- node GEMM (high-ILP) + folded attention dots ---------------
// 16 nodes per block-iteration. Thread owns 1 output column x 4 nodes:
// inner loop = 4 independent LDS.128 feeding 16 FFMAs (4:1 FMA:LDS).
// a_s/a_d computed per warp from xsh against precomputed ws/wd (no block sync).
__global__ void node_gemm_kernel(const float* __restrict__ xin,
                                 const float* __restrict__ addb,   // may be null
                                 const float* __restrict__ W,
                                 const float* __restrict__ wsv,
                                 const float* __restrict__ wdv,
                                 float* __restrict__ hout,
                                 float* __restrict__ as_out,
                                 float* __restrict__ ad_out) {
    __shared__ float  Wsh[HID * HID];
    __shared__ float4 xsh[16 * 16];       // 16 nodes x 64 floats
    __shared__ float  wssh[HID];
    __shared__ float  wdsh[HID];

    int tid  = threadIdx.x;
    int j    = tid & 63;
    int sub  = tid >> 6;
    int lane = tid & 31;
    int warp = tid >> 5;

    for (int i = tid; i < HID * HID; i += 256) Wsh[i] = W[i];
    if (tid < HID) { wssh[tid] = wsv[tid]; wdsh[tid] = wdv[tid]; }
    __syncthreads();

    float wreg[HID];
    #pragma unroll
    for (int k = 0; k < HID; k++) wreg[k] = Wsh[k * HID + j];

    // bias float4 for this thread's fixed load column (tid&15)
    float4 ab = make_float4(0.f, 0.f, 0.f, 0.f);
    if (addb != nullptr) ab = ((const float4*)addb)[tid & 15];

    const float* xf = (const float*)xsh;

    for (int base = blockIdx.x * 16; base < N_NODES; base += gridDim.x * 16) {
        __syncthreads();     // protect xsh reuse across iterations
        float4 v = __ldg((const float4*)(xin + (size_t)base * HID) + tid);
        v.x += ab.x; v.y += ab.y; v.z += ab.z; v.w += ab.w;
        xsh[tid] = v;
        __syncthreads();

        float acc0 = 0.f, acc1 = 0.f, acc2 = 0.f, acc3 = 0.f;
        const float4* xr0 = &xsh[(sub * 4 + 0) * 16];
        const float4* xr1 = &xsh[(sub * 4 + 1) * 16];
        const float4* xr2 = &xsh[(sub * 4 + 2) * 16];
        const float4* xr3 = &xsh[(sub * 4 + 3) * 16];
        #pragma unroll
        for (int k4 = 0; k4 < 16; k4++) {
            float w0 = wreg[4*k4], w1 = wreg[4*k4+1], w2 = wreg[4*k4+2], w3 = wreg[4*k4+3];
            float4 a = xr0[k4]; acc0 += a.x*w0 + a.y*w1 + a.z*w2 + a.w*w3;
            float4 b = xr1[k4]; acc1 += b.x*w0 + b.y*w1 + b.z*w2 + b.w*w3;
            float4 c = xr2[k4]; acc2 += c.x*w0 + c.y*w1 + c.z*w2 + c.w*w3;
            float4 d = xr3[k4]; acc3 += d.x*w0 + d.y*w1 + d.z*w2 + d.w*w3;
        }
        int nb = base + sub * 4;
        hout[(size_t)(nb + 0) * HID + j] = acc0;
        hout[(size_t)(nb + 1) * HID + j] = acc1;
        hout[(size_t)(nb + 2) * HID + j] = acc2;
        hout[(size_t)(nb + 3) * HID + j] = acc3;

        // attention dots: warp w handles nodes 2w, 2w+1 (reads xsh only)
        #pragma unroll
        for (int m = 0; m < 2; m++) {
            int node = warp * 2 + m;
            float xa = xf[node * HID + lane];
            float xb = xf[node * HID + lane + 32];
            float sv = xa * wssh[lane] + xb * wssh[lane + 32];
            float dv = xa * wdsh[lane] + xb * wdsh[lane + 32];
            #pragma unroll
            for (int o = 16; o > 0; o >>= 1) {
                sv += __shfl_xor_sync(0xffffffffu, sv, o);
                dv += __shfl_xor_sync(0xffffffffu, dv, o);
            }
            if (lane == 0) { as_out[base + node] = sv; ad_out[base + node] = dv; }
        }
    }
}

// ---------------- gather-only attention aggregate (atomic-free) --------------
// Warp per dst node; two half-warp chains; lane l owns features [4l,4l+4).
// Software-pipelined edge-record prefetch. LAYER==1 fuses residual+bias+pool.
template<int LAYER>
__global__ void agg_kernel(const float* __restrict__ h,
                           float* __restrict__ aggout,
                           const float* __restrict__ b0,
                           const float* __restrict__ b1) {
    int warp = (blockIdx.x * blockDim.x + threadIdx.x) >> 5;
    int lane = threadIdx.x & 31;
    int half = lane >> 4;
    int l    = lane & 15;
    int n    = warp;
    if (n >= N_NODES) return;

    int start = g_off[n];
    int end   = g_off[n + 1];
    float adn = g_ad[n];

    float4 acc = make_float4(0.f, 0.f, 0.f, 0.f);
    float dacc = 0.f;

    int i = start + half;
    float4 er = make_float4(0.f, 0.f, 0.f, 0.f);
    if (i < end) er = g_edges[i];
    while (i < end) {
        int inext = i + 2;
        float4 er2 = make_float4(0.f, 0.f, 0.f, 0.f);
        if (inext < end) er2 = g_edges[inext];        // prefetch overlaps gathers

        int   src = __float_as_int(er.x);
        float ae  = (LAYER == 0) ? er.y : er.z;
        float4 hv = ((const float4*)h)[(size_t)src * 16 + l];
        float al  = g_as[src] + adn + ae;
        al = (al > 0.f) ? al : 0.2f * al;             // leaky relu
        float p = __expf(al);                         // no max-sub (softmax invariant)
        acc.x += p * hv.x; acc.y += p * hv.y;
        acc.z += p * hv.z; acc.w += p * hv.w;
        dacc  += p;

        er = er2;
        i  = inext;
    }

    acc.x += __shfl_xor_sync(0xffffffffu, acc.x, 16);
    acc.y += __shfl_xor_sync(0xffffffffu, acc.y, 16);
    acc.z += __shfl_xor_sync(0xffffffffu, acc.z, 16);
    acc.w += __shfl_xor_sync(0xffffffffu, acc.w, 16);
    dacc  += __shfl_xor_sync(0xffffffffu, dacc,  16);

    if (half == 0) {
        float r = 1.f / (dacc + 1e-16f);
        if (LAYER == 0) {
            ((float4*)aggout)[(size_t)n * 16 + l] =
                make_float4(acc.x * r, acc.y * r, acc.z * r, acc.w * r);
        } else {
            float4 v0  = ((const float4*)g_agg0)[(size_t)n * 16 + l];
            float4 bb0 = ((const float4*)b0)[l];
            float4 bb1 = ((const float4*)b1)[l];
            int g = g_batch[n];
            red_add_v4(&g_gsum[g * HID + 4 * l],
                       acc.x * r + v0.x + bb0.x + bb1.x,
                       acc.y * r + v0.y + bb0.y + bb1.y,
                       acc.z * r + v0.z + bb0.z + bb1.z,
                       acc.w * r + v0.w + bb0.w + bb1.w);
        }
    }
}

__global__ void finalize_kernel(float* __restrict__ out) {
    int i = blockIdx.x * HID + threadIdx.x;   // 256 blocks x 64 threads
    int g = i >> 6;
    float c = g_gcnt[g];
    if (c < 1.f) c = 1.f;
    out[i] = g_gsum[i] / c;
}

// ---------------- launcher ---------------------------------------------------
extern "C" void kernel_launch(void* const* d_in, const int* in_sizes, int n_in,
                              void* d_out, int out_size) {
    const float* x     = (const float*)d_in[0];
    const void*  ei    = d_in[1];
    const float* ea    = (const float*)d_in[2];
    const void*  batch = d_in[3];
    const float* W0   = (const float*)d_in[4];
    const float* as0  = (const float*)d_in[5];
    const float* ad0  = (const float*)d_in[6];
    const float* We0  = (const float*)d_in[7];
    const float* ae0v = (const float*)d_in[8];
    const float* b0   = (const float*)d_in[9];
    const float* W1   = (const float*)d_in[10];
    const float* as1  = (const float*)d_in[11];
    const float* ad1  = (const float*)d_in[12];
    const float* We1  = (const float*)d_in[13];
    const float* ae1v = (const float*)d_in[14];
    const float* b1   = (const float*)d_in[15];
    float* out = (float*)d_out;

    void *p_cnt, *p_gsum, *p_gcnt, *p_h, *p_as, *p_ad, *p_agg0;
    void *p_ws0, *p_wd0, *p_ws1, *p_wd1;
    cudaGetSymbolAddress(&p_cnt,  g_cnt);
    cudaGetSymbolAddress(&p_gsum, g_gsum);
    cudaGetSymbolAddress(&p_gcnt, g_gcnt);
    cudaGetSymbolAddress(&p_h,    g_h);
    cudaGetSymbolAddress(&p_as,   g_as);
    cudaGetSymbolAddress(&p_ad,   g_ad);
    cudaGetSymbolAddress(&p_agg0, g_agg0);
    cudaGetSymbolAddress(&p_ws0,  g_ws0);
    cudaGetSymbolAddress(&p_wd0,  g_wd0);
    cudaGetSymbolAddress(&p_ws1,  g_ws1);
    cudaGetSymbolAddress(&p_wd1,  g_wd1);

    float* hbuf = (float*)p_h;
    float* asb  = (float*)p_as;
    float* adb  = (float*)p_ad;

    // zero accumulators
    cudaMemsetAsync(p_cnt,  0, N_NODES * sizeof(int));
    cudaMemsetAsync(p_gsum, 0, N_GRAPHS * HID * sizeof(float));
    cudaMemsetAsync(p_gcnt, 0, N_GRAPHS * sizeof(float));

    // index conversion + CSR build
    detect_dtype_kernel<<<1, 64>>>(ei);
    convert_edges_kernel<<<(N_EDGES + 255) / 256, 256>>>(ei);
    convert_batch_kernel<<<(N_NODES + 255) / 256, 256>>>(batch);
    scan1_kernel<<<N_SCAN_BLKS, SCAN_BLK>>>();
    scan2_kernel<<<1, 128>>>();
    scan3_kernel<<<N_SCAN_BLKS, SCAN_BLK>>>();
    prep_kernel<<<1, 64>>>(We0, ae0v, We1, ae1v, W0, as0, ad0, W1, as1, ad1);
    build_csr_kernel<<<(N_EDGES + 255) / 256, 256>>>(ea);

    // ---- layer 0 ----
    node_gemm_kernel<<<1250, 256>>>(x, nullptr, W0, (const float*)p_ws0, (const float*)p_wd0,
                                    hbuf, asb, adb);
    agg_kernel<0><<<(N_NODES * 32 + 255) / 256, 256>>>(hbuf, (float*)p_agg0, b0, b1);

    // ---- layer 1 (input = normalized agg0 + b0, fused into gemm load;
    //      agg pass fuses residual + bias + pool) ----
    node_gemm_kernel<<<1250, 256>>>((const float*)p_agg0, b0, W1,
                                    (const float*)p_ws1, (const float*)p_wd1,
                                    hbuf, asb, adb);
    agg_kernel<1><<<(N_NODES * 32 + 255) / 256, 256>>>(hbuf, nullptr, b0, b1);

    // ---- finalize (divide by per-graph counts) ----
    finalize_kernel<<<N_GRAPHS, HID>>>(out);
}

// round 11
// speedup vs baseline: 1.2927x; 1.0122x over previous
#include <cuda_runtime.h>
#include <cstdint>

#define N_NODES  100000
#define N_EDGES  1000000
#define HID      64
#define EDGE_D   32
#define N_GRAPHS 256
#define SCAN_BLK 1024
#define N_SCAN_BLKS ((N_NODES + SCAN_BLK - 1) / SCAN_BLK)   // 98

// ---------------- scratch (static device globals; no allocation) -------------
__device__ float g_h[N_NODES * HID];      // node features after lin (per layer)
__device__ float g_agg0[N_NODES * HID];   // layer0 NORMALIZED aggregate
__device__ float g_as[N_NODES];           // source attention logits
__device__ float g_ad[N_NODES];           // dest attention logits
__device__ float g_we0[EDGE_D];           // We0 @ att_edge0
__device__ float g_we1[EDGE_D];           // We1 @ att_edge1
__device__ float g_ws0[HID];              // W0 @ att_src0
__device__ float g_wd0[HID];              // W0 @ att_dst0
__device__ float g_ws1[HID];              // W1 @ att_src1
__device__ float g_wd1[HID];              // W1 @ att_dst1
__device__ float g_gsum[N_GRAPHS * HID];
__device__ float g_gcnt[N_GRAPHS];
__device__ int   g_src[N_EDGES];
__device__ int   g_dst[N_EDGES];
__device__ int   g_batch[N_NODES];
__device__ int   g_is32;
__device__ int   g_cnt[N_NODES];          // in-degree histogram
__device__ int   g_off[N_NODES + 1];      // CSR offsets
__device__ int   g_cur[N_NODES];          // scatter cursors
__device__ int   g_bsum[128];             // scan block sums
__device__ int   g_bexcl[128];            // scanned block sums
__device__ float4 g_edges[N_EDGES];       // packed {src_bits, ae0, ae1, pad}, dst-sorted

// ---------------- vectorized global reductions (sm_90+) ----------------------
__device__ __forceinline__ void red_add_v4(float* addr, float x, float y, float z, float w) {
    asm volatile(
        "{ .reg .u64 a; cvta.to.global.u64 a, %0; red.global.add.v4.f32 [a], {%1,%2,%3,%4}; }"
        :: "l"(addr), "f"(x), "f"(y), "f"(z), "f"(w) : "memory");
}
__device__ __forceinline__ void red_add_f32(float* addr, float x) {
    asm volatile(
        "{ .reg .u64 a; cvta.to.global.u64 a, %0; red.global.add.f32 [a], %1; }"
        :: "l"(addr), "f"(x) : "memory");
}

// packed f32x2 fused multiply-add: d = a*b + d (elementwise on 2 floats)
__device__ __forceinline__ void fma2(unsigned long long& d,
                                     unsigned long long a, unsigned long long b) {
    asm("fma.rn.f32x2 %0, %1, %2, %0;" : "+l"(d) : "l"(a), "l"(b));
}
__device__ __forceinline__ float f32x2_hadd(unsigned long long v) {
    float lo, hi;
    asm("mov.b64 {%0, %1}, %2;" : "=f"(lo), "=f"(hi) : "l"(v));
    return lo + hi;
}

// ---------------- dtype detection: int32 vs int64 edge_index -----------------
__global__ void detect_dtype_kernel(const void* __restrict__ ei_raw) {
    const unsigned int* w = (const unsigned int*)ei_raw;
    int t = threadIdx.x;
    unsigned int hi = w[2 * t + 1];
    unsigned int any = __syncthreads_or(hi != 0u);
    if (t == 0) g_is32 = (any != 0u) ? 1 : 0;
}

// convert indices + build in-degree histogram
__global__ void convert_edges_kernel(const void* __restrict__ ei_raw) {
    int e = blockIdx.x * blockDim.x + threadIdx.x;
    if (e >= N_EDGES) return;
    int s, d;
    if (g_is32) {
        const int* p = (const int*)ei_raw;
        s = p[e]; d = p[N_EDGES + e];
    } else {
        const long long* p = (const long long*)ei_raw;
        s = (int)p[e]; d = (int)p[N_EDGES + e];
    }
    g_src[e] = s;
    g_dst[e] = d;
    atomicAdd(&g_cnt[d], 1);
}

// convert batch indices + accumulate per-graph node counts
__global__ void convert_batch_kernel(const void* __restrict__ b_raw) {
    int n = blockIdx.x * blockDim.x + threadIdx.x;
    if (n >= N_NODES) return;
    int g;
    if (g_is32) g = ((const int*)b_raw)[n];
    else        g = (int)((const long long*)b_raw)[n];
    g_batch[n] = g;
    red_add_f32(&g_gcnt[g], 1.0f);
}

// ---------------- 2-level exclusive scan of g_cnt -> g_off -------------------
__global__ void scan1_kernel() {
    __shared__ int sh[SCAN_BLK];
    int tid = threadIdx.x;
    int i = blockIdx.x * SCAN_BLK + tid;
    int v = (i < N_NODES) ? g_cnt[i] : 0;
    sh[tid] = v;
    __syncthreads();
    for (int ofs = 1; ofs < SCAN_BLK; ofs <<= 1) {
        int t = (tid >= ofs) ? sh[tid - ofs] : 0;
        __syncthreads();
        sh[tid] += t;
        __syncthreads();
    }
    if (i < N_NODES) g_off[i] = sh[tid] - v;       // exclusive within block
    if (tid == SCAN_BLK - 1) g_bsum[blockIdx.x] = sh[tid];
}

__global__ void scan2_kernel() {
    __shared__ int sh[128];
    int tid = threadIdx.x;
    int v = (tid < N_SCAN_BLKS) ? g_bsum[tid] : 0;
    sh[tid] = v;
    __syncthreads();
    for (int ofs = 1; ofs < 128; ofs <<= 1) {
        int t = (tid >= ofs) ? sh[tid - ofs] : 0;
        __syncthreads();
        sh[tid] += t;
        __syncthreads();
    }
    g_bexcl[tid] = sh[tid] - v;                    // exclusive
}

__global__ void scan3_kernel() {
    int i = blockIdx.x * SCAN_BLK + threadIdx.x;
    if (i < N_NODES) {
        int o = g_off[i] + g_bexcl[blockIdx.x];
        g_off[i] = o;
        g_cur[i] = o;
    }
    if (i == 0) g_off[N_NODES] = N_EDGES;
}

// ---------------- precompute folded attention vectors ------------------------
__global__ void prep_kernel(const float* __restrict__ We0, const float* __restrict__ ae0,
                            const float* __restrict__ We1, const float* __restrict__ ae1,
                            const float* __restrict__ W0,  const float* __restrict__ as0,
                            const float* __restrict__ ad0,
                            const float* __restrict__ W1,  const float* __restrict__ as1,
                            const float* __restrict__ ad1) {
    int t = threadIdx.x;   // 64 threads
    if (t < EDGE_D) {
        float s0 = 0.f, s1 = 0.f;
        #pragma unroll
        for (int j = 0; j < HID; j++) {
            s0 += We0[t * HID + j] * ae0[j];
            s1 += We1[t * HID + j] * ae1[j];
        }
        g_we0[t] = s0;
        g_we1[t] = s1;
    }
    float vs0 = 0.f, vd0 = 0.f, vs1 = 0.f, vd1 = 0.f;
    #pragma unroll
    for (int j = 0; j < HID; j++) {
        float w0 = W0[t * HID + j];
        float w1 = W1[t * HID + j];
        vs0 += w0 * as0[j];  vd0 += w0 * ad0[j];
        vs1 += w1 * as1[j];  vd1 += w1 * ad1[j];
    }
    g_ws0[t] = vs0;  g_wd0[t] = vd0;
    g_ws1[t] = vs1;  g_wd1[t] = vd1;
}

// ---------------- CSR build: bucket-scatter packed edge records --------------
__global__ void build_csr_kernel(const float* __restrict__ ea) {
    __shared__ float sw0[EDGE_D];
    __shared__ float sw1[EDGE_D];
    int tid = threadIdx.x;
    if (tid < EDGE_D) sw0[tid] = g_we0[tid];
    else if (tid < 2 * EDGE_D) sw1[tid - EDGE_D] = g_we1[tid - EDGE_D];
    __syncthreads();

    int e = blockIdx.x * blockDim.x + tid;
    if (e >= N_EDGES) return;

    const float4* row = (const float4*)(ea + (size_t)e * EDGE_D);
    float ae0 = 0.f, ae1 = 0.f;
    #pragma unroll
    for (int i = 0; i < EDGE_D / 4; i++) {
        float4 v = __ldg(&row[i]);
        ae0 += v.x * sw0[4*i] + v.y * sw0[4*i+1] + v.z * sw0[4*i+2] + v.w * sw0[4*i+3];
        ae1 += v.x * sw1[4*i] + v.y * sw1[4*i+1] + v.z * sw1[4*i+2] + v.w * sw1[4*i+3];
    }

    int d = g_dst[e];
    int pos = atomicAdd(&g_cur[d], 1);
    g_edges[pos] = make_float4(__int_as_float(g_src[e]), ae0, ae1, 0.f);
}

// ---------------- node GEMM (f32x2 packed FMA) + folded attention dots -------
// 16 nodes per block-iteration. Thread owns 1 output column x 4 nodes.
// W column held as 32 packed (w2k, w2k+1) b64 pairs; x float4 reinterpreted as
// two b64 pairs -> 8 fma.rn.f32x2 per k4-step (half the FP-issue of scalar).
__global__ void node_gemm_kernel(const float* __restrict__ xin,
                                 const float* __restrict__ addb,   // may be null
                                 const float* __restrict__ W,
                                 const float* __restrict__ wsv,
                                 const float* __restrict__ wdv,
                                 float* __restrict__ hout,
                                 float* __restrict__ as_out,
                                 float* __restrict__ ad_out) {
    __shared__ float  Wsh[HID * HID];
    __shared__ float4 xsh[16 * 16];       // 16 nodes x 64 floats
    __shared__ float  wssh[HID];
    __shared__ float  wdsh[HID];

    int tid  = threadIdx.x;
    int j    = tid & 63;
    int sub  = tid >> 6;
    int lane = tid & 31;
    int warp = tid >> 5;

    for (int i = tid; i < HID * HID; i += 256) Wsh[i] = W[i];
    if (tid < HID) { wssh[tid] = wsv[tid]; wdsh[tid] = wdv[tid]; }
    __syncthreads();

    // packed W column: wp[k2] = (W[2k2][j], W[2k2+1][j])
    unsigned long long wp[HID / 2];
    #pragma unroll
    for (int k2 = 0; k2 < HID / 2; k2++) {
        float lo = Wsh[(2 * k2)     * HID + j];
        float hi = Wsh[(2 * k2 + 1) * HID + j];
        asm("mov.b64 %0, {%1, %2};" : "=l"(wp[k2]) : "f"(lo), "f"(hi));
    }

    // bias float4 for this thread's fixed load column (tid&15)
    float4 ab = make_float4(0.f, 0.f, 0.f, 0.f);
    if (addb != nullptr) ab = ((const float4*)addb)[tid & 15];

    const float* xf = (const float*)xsh;

    for (int base = blockIdx.x * 16; base < N_NODES; base += gridDim.x * 16) {
        __syncthreads();     // protect xsh reuse across iterations
        float4 v = __ldg((const float4*)(xin + (size_t)base * HID) + tid);
        v.x += ab.x; v.y += ab.y; v.z += ab.z; v.w += ab.w;
        xsh[tid] = v;
        __syncthreads();

        unsigned long long acc0 = 0ull, acc1 = 0ull, acc2 = 0ull, acc3 = 0ull;
        const ulonglong2* xr0 = (const ulonglong2*)&xsh[(sub * 4 + 0) * 16];
        const ulonglong2* xr1 = (const ulonglong2*)&xsh[(sub * 4 + 1) * 16];
        const ulonglong2* xr2 = (const ulonglong2*)&xsh[(sub * 4 + 2) * 16];
        const ulonglong2* xr3 = (const ulonglong2*)&xsh[(sub * 4 + 3) * 16];
        #pragma unroll
        for (int k4 = 0; k4 < 16; k4++) {
            unsigned long long w01 = wp[2 * k4], w23 = wp[2 * k4 + 1];
            ulonglong2 a = xr0[k4]; fma2(acc0, a.x, w01); fma2(acc0, a.y, w23);
            ulonglong2 b = xr1[k4]; fma2(acc1, b.x, w01); fma2(acc1, b.y, w23);
            ulonglong2 c = xr2[k4]; fma2(acc2, c.x, w01); fma2(acc2, c.y, w23);
            ulonglong2 d = xr3[k4]; fma2(acc3, d.x, w01); fma2(acc3, d.y, w23);
        }
        int nb = base + sub * 4;
        hout[(size_t)(nb + 0) * HID + j] = f32x2_hadd(acc0);
        hout[(size_t)(nb + 1) * HID + j] = f32x2_hadd(acc1);
        hout[(size_t)(nb + 2) * HID + j] = f32x2_hadd(acc2);
        hout[(size_t)(nb + 3) * HID + j] = f32x2_hadd(acc3);

        // attention dots: warp w handles nodes 2w, 2w+1 (reads xsh only)
        #pragma unroll
        for (int m = 0; m < 2; m++) {
            int node = warp * 2 + m;
            float xa = xf[node * HID + lane];
            float xb = xf[node * HID + lane + 32];
            float sv = xa * wssh[lane] + xb * wssh[lane + 32];
            float dv = xa * wdsh[lane] + xb * wdsh[lane + 32];
            #pragma unroll
            for (int o = 16; o > 0; o >>= 1) {
                sv += __shfl_xor_sync(0xffffffffu, sv, o);
                dv += __shfl_xor_sync(0xffffffffu, dv, o);
            }
            if (lane == 0) { as_out[base + node] = sv; ad_out[base + node] = dv; }
        }
    }
}

// ---------------- gather-only attention aggregate (atomic-free) --------------
template<int LAYER>
__global__ void agg_kernel(const float* __restrict__ h,
                           float* __restrict__ aggout,
                           const float* __restrict__ b0,
                           const float* __restrict__ b1) {
    int warp = (blockIdx.x * blockDim.x + threadIdx.x) >> 5;
    int lane = threadIdx.x & 31;
    int half = lane >> 4;
    int l    = lane & 15;
    int n    = warp;
    if (n >= N_NODES) return;

    int start = g_off[n];
    int end   = g_off[n + 1];
    float adn = g_ad[n];

    float4 acc = make_float4(0.f, 0.f, 0.f, 0.f);
    float dacc = 0.f;

    int i = start + half;
    float4 er = make_float4(0.f, 0.f, 0.f, 0.f);
    if (i < end) er = g_edges[i];
    while (i < end) {
        int inext = i + 2;
        float4 er2 = make_float4(0.f, 0.f, 0.f, 0.f);
        if (inext < end) er2 = g_edges[inext];        // prefetch overlaps gathers

        int   src = __float_as_int(er.x);
        float ae  = (LAYER == 0) ? er.y : er.z;
        float4 hv = ((const float4*)h)[(size_t)src * 16 + l];
        float al  = g_as[src] + adn + ae;
        al = (al > 0.f) ? al : 0.2f * al;             // leaky relu
        float p = __expf(al);                         // no max-sub (softmax invariant)
        acc.x += p * hv.x; acc.y += p * hv.y;
        acc.z += p * hv.z; acc.w += p * hv.w;
        dacc  += p;

        er = er2;
        i  = inext;
    }

    acc.x += __shfl_xor_sync(0xffffffffu, acc.x, 16);
    acc.y += __shfl_xor_sync(0xffffffffu, acc.y, 16);
    acc.z += __shfl_xor_sync(0xffffffffu, acc.z, 16);
    acc.w += __shfl_xor_sync(0xffffffffu, acc.w, 16);
    dacc  += __shfl_xor_sync(0xffffffffu, dacc,  16);

    if (half == 0) {
        float r = 1.f / (dacc + 1e-16f);
        if (LAYER == 0) {
            ((float4*)aggout)[(size_t)n * 16 + l] =
                make_float4(acc.x * r, acc.y * r, acc.z * r, acc.w * r);
        } else {
            float4 v0  = ((const float4*)g_agg0)[(size_t)n * 16 + l];
            float4 bb0 = ((const float4*)b0)[l];
            float4 bb1 = ((const float4*)b1)[l];
            int g = g_batch[n];
            red_add_v4(&g_gsum[g * HID + 4 * l],
                       acc.x * r + v0.x + bb0.x + bb1.x,
                       acc.y * r + v0.y + bb0.y + bb1.y,
                       acc.z * r + v0.z + bb0.z + bb1.z,
                       acc.w * r + v0.w + bb0.w + bb1.w);
        }
    }
}

__global__ void finalize_kernel(float* __restrict__ out) {
    int i = blockIdx.x * HID + threadIdx.x;   // 256 blocks x 64 threads
    int g = i >> 6;
    float c = g_gcnt[g];
    if (c < 1.f) c = 1.f;
    out[i] = g_gsum[i] / c;
}

// ---------------- launcher ---------------------------------------------------
extern "C" void kernel_launch(void* const* d_in, const int* in_sizes, int n_in,
                              void* d_out, int out_size) {
    const float* x     = (const float*)d_in[0];
    const void*  ei    = d_in[1];
    const float* ea    = (const float*)d_in[2];
    const void*  batch = d_in[3];
    const float* W0   = (const float*)d_in[4];
    const float* as0  = (const float*)d_in[5];
    const float* ad0  = (const float*)d_in[6];
    const float* We0  = (const float*)d_in[7];
    const float* ae0v = (const float*)d_in[8];
    const float* b0   = (const float*)d_in[9];
    const float* W1   = (const float*)d_in[10];
    const float* as1  = (const float*)d_in[11];
    const float* ad1  = (const float*)d_in[12];
    const float* We1  = (const float*)d_in[13];
    const float* ae1v = (const float*)d_in[14];
    const float* b1   = (const float*)d_in[15];
    float* out = (float*)d_out;

    void *p_cnt, *p_gsum, *p_gcnt, *p_h, *p_as, *p_ad, *p_agg0;
    void *p_ws0, *p_wd0, *p_ws1, *p_wd1;
    cudaGetSymbolAddress(&p_cnt,  g_cnt);
    cudaGetSymbolAddress(&p_gsum, g_gsum);
    cudaGetSymbolAddress(&p_gcnt, g_gcnt);
    cudaGetSymbolAddress(&p_h,    g_h);
    cudaGetSymbolAddress(&p_as,   g_as);
    cudaGetSymbolAddress(&p_ad,   g_ad);
    cudaGetSymbolAddress(&p_agg0, g_agg0);
    cudaGetSymbolAddress(&p_ws0,  g_ws0);
    cudaGetSymbolAddress(&p_wd0,  g_wd0);
    cudaGetSymbolAddress(&p_ws1,  g_ws1);
    cudaGetSymbolAddress(&p_wd1,  g_wd1);

    float* hbuf = (float*)p_h;
    float* asb  = (float*)p_as;
    float* adb  = (float*)p_ad;

    // zero accumulators
    cudaMemsetAsync(p_cnt,  0, N_NODES * sizeof(int));
    cudaMemsetAsync(p_gsum, 0, N_GRAPHS * HID * sizeof(float));
    cudaMemsetAsync(p_gcnt, 0, N_GRAPHS * sizeof(float));

    // Launch order is dependency-equivalent to R9 but places gemm0 at kernel
    // slot #4 so the auto-profiler captures it (empirical: slot 4 is captured).
    detect_dtype_kernel<<<1, 64>>>(ei);
    prep_kernel<<<1, 64>>>(We0, ae0v, We1, ae1v, W0, as0, ad0, W1, as1, ad1);
    convert_edges_kernel<<<(N_EDGES + 255) / 256, 256>>>(ei);

    // ---- layer 0 GEMM (slot #4) ----
    node_gemm_kernel<<<1250, 256>>>(x, nullptr, W0, (const float*)p_ws0, (const float*)p_wd0,
                                    hbuf, asb, adb);

    convert_batch_kernel<<<(N_NODES + 255) / 256, 256>>>(batch);
    scan1_kernel<<<N_SCAN_BLKS, SCAN_BLK>>>();
    scan2_kernel<<<1, 128>>>();
    scan3_kernel<<<N_SCAN_BLKS, SCAN_BLK>>>();
    build_csr_kernel<<<(N_EDGES + 255) / 256, 256>>>(ea);

    // ---- layer 0 aggregate ----
    agg_kernel<0><<<(N_NODES * 32 + 255) / 256, 256>>>(hbuf, (float*)p_agg0, b0, b1);

    // ---- layer 1 (input = normalized agg0 + b0, fused into gemm load;
    //      agg pass fuses residual + bias + pool) ----
    node_gemm_kernel<<<1250, 256>>>((const float*)p_agg0, b0, W1,
                                    (const float*)p_ws1, (const float*)p_wd1,
                                    hbuf, asb, adb);
    agg_kernel<1><<<(N_NODES * 32 + 255) / 256, 256>>>(hbuf, nullptr, b0, b1);

    // ---- finalize (divide by per-graph counts) ----
    finalize_kernel<<<N_GRAPHS, HID>>>(out);
}